// round 2
// baseline (speedup 1.0000x reference)
#include <cuda_runtime.h>
#include <math.h>

#define N_ROWS   131072            // B*K = 32*4096
#define C_CODES  1024
#define D_DIM    64
#define NZQ      8388608           // N_ROWS * D_DIM
#define OUT_LOSS NZQ               // offset of scalar loss
#define OUT_IDX  (NZQ + 1)         // offset of indices

// Scratch (device globals: allocation-free per harness rules)
__device__ float g_dist[(size_t)N_ROWS * C_CODES];   // 512 MB shifted distances
__device__ float g_rowmin[N_ROWS];
__device__ int   g_idx[N_ROWS];
__device__ float g_wsq[C_CODES];
__device__ float g_avg[C_CODES];
__device__ float g_mse;

// ---------------------------------------------------------------------------
// kernel 0: per-code squared norms + zero accumulators
// ---------------------------------------------------------------------------
__global__ void k_init(const float* __restrict__ cb) {
    int t = blockIdx.x * 256 + threadIdx.x;
    if (t < C_CODES) {
        const float4* p = (const float4*)(cb + (size_t)t * D_DIM);
        float s = 0.f;
        #pragma unroll
        for (int q = 0; q < D_DIM / 4; q++) {
            float4 v = p[q];
            s += v.x * v.x + v.y * v.y + v.z * v.z + v.w * v.w;
        }
        g_wsq[t] = s;
        g_avg[t] = 0.f;
    }
    if (t == 0) g_mse = 0.f;
}

// ---------------------------------------------------------------------------
// kernel 1: distance GEMM + argmin/min, spill shifted distances to scratch
// block: 256 threads, 64 rows x 1024 codes (8 chunks of 128 codes)
// warp w owns rows [w*8, w*8+8); lane owns codes [lane*4, lane*4+4) per chunk
// ---------------------------------------------------------------------------
__global__ __launch_bounds__(256) void k_dist(const float* __restrict__ z,
                                              const float* __restrict__ cb) {
    extern __shared__ float smem[];
    float* sZt = smem;                 // [64 k][64 rows]   16 KB (transposed)
    float* sB  = smem + 64 * 64;       // [64 k][128 codes] 32 KB (transposed)
    float* sW  = smem + 64 * 64 + 64 * 128;  // [128]        0.5 KB

    const int tid  = threadIdx.x;
    const int lane = tid & 31;
    const int w    = tid >> 5;         // warp id 0..7
    const int w8   = w * 8;
    const int lane4 = lane * 4;
    const size_t rowBase = (size_t)blockIdx.x * 64;

    // load z tile, transposed: sZt[k][r]
    {
        int r  = tid & 63;
        int kq = tid >> 6;             // 0..3, 16 k's each
        const float4* zp = (const float4*)(z + (rowBase + r) * D_DIM);
        #pragma unroll
        for (int q = 0; q < 4; q++) {
            float4 v = zp[kq * 4 + q];
            int k0 = kq * 16 + q * 4;
            sZt[(k0 + 0) * 64 + r] = v.x;
            sZt[(k0 + 1) * 64 + r] = v.y;
            sZt[(k0 + 2) * 64 + r] = v.z;
            sZt[(k0 + 3) * 64 + r] = v.w;
        }
    }

    float bestd[8];
    int   bestc[8];
    #pragma unroll
    for (int i = 0; i < 8; i++) { bestd[i] = 3.4e38f; bestc[i] = 0; }

    #pragma unroll 1
    for (int ch = 0; ch < 8; ch++) {
        __syncthreads();   // also covers initial z-tile visibility
        // load codebook chunk, transposed: sB[k][c]
        {
            int c  = tid & 127;
            int kq = tid >> 7;         // 0..1, 32 k's each
            const float4* bp = (const float4*)(cb + (size_t)(ch * 128 + c) * D_DIM);
            #pragma unroll
            for (int q = 0; q < 8; q++) {
                float4 v = bp[kq * 8 + q];
                int k0 = kq * 32 + q * 4;
                sB[(k0 + 0) * 128 + c] = v.x;
                sB[(k0 + 1) * 128 + c] = v.y;
                sB[(k0 + 2) * 128 + c] = v.z;
                sB[(k0 + 3) * 128 + c] = v.w;
            }
            if (tid < 128) sW[tid] = g_wsq[ch * 128 + tid];
        }
        __syncthreads();

        float acc[8][4];
        #pragma unroll
        for (int i = 0; i < 8; i++)
            #pragma unroll
            for (int j = 0; j < 4; j++) acc[i][j] = 0.f;

        #pragma unroll 8
        for (int k = 0; k < 64; k++) {
            float4 a0 = *(const float4*)&sZt[k * 64 + w8];
            float4 a1 = *(const float4*)&sZt[k * 64 + w8 + 4];
            float4 bb = *(const float4*)&sB[k * 128 + lane4];
            float a_[8] = {a0.x, a0.y, a0.z, a0.w, a1.x, a1.y, a1.z, a1.w};
            float b_[4] = {bb.x, bb.y, bb.z, bb.w};
            #pragma unroll
            for (int i = 0; i < 8; i++)
                #pragma unroll
                for (int j = 0; j < 4; j++)
                    acc[i][j] = fmaf(a_[i], b_[j], acc[i][j]);
        }

        // epilogue: shifted dist = ||w||^2 - 2*dot ; track min/argmin; spill
        const int cbase = ch * 128 + lane4;
        const float w0 = sW[lane4 + 0], w1 = sW[lane4 + 1];
        const float w2 = sW[lane4 + 2], w3 = sW[lane4 + 3];
        #pragma unroll
        for (int i = 0; i < 8; i++) {
            float4 dv;
            dv.x = fmaf(-2.f, acc[i][0], w0);
            dv.y = fmaf(-2.f, acc[i][1], w1);
            dv.z = fmaf(-2.f, acc[i][2], w2);
            dv.w = fmaf(-2.f, acc[i][3], w3);
            if (dv.x < bestd[i]) { bestd[i] = dv.x; bestc[i] = cbase + 0; }
            if (dv.y < bestd[i]) { bestd[i] = dv.y; bestc[i] = cbase + 1; }
            if (dv.z < bestd[i]) { bestd[i] = dv.z; bestc[i] = cbase + 2; }
            if (dv.w < bestd[i]) { bestd[i] = dv.w; bestc[i] = cbase + 3; }
            *(float4*)(g_dist + (rowBase + w8 + i) * (size_t)C_CODES + cbase) = dv;
        }
    }

    // warp-level argmin reduce (tie -> smaller index, matching jnp.argmin)
    #pragma unroll
    for (int i = 0; i < 8; i++) {
        float d = bestd[i];
        int   c = bestc[i];
        #pragma unroll
        for (int off = 16; off > 0; off >>= 1) {
            float od = __shfl_xor_sync(0xffffffffu, d, off);
            int   oc = __shfl_xor_sync(0xffffffffu, c, off);
            if (od < d || (od == d && oc < c)) { d = od; c = oc; }
        }
        if (lane == 0) {
            g_rowmin[rowBase + w8 + i] = d;
            g_idx[rowBase + w8 + i]    = c;
        }
    }
}

// ---------------------------------------------------------------------------
// kernel 2: per-row softmax Z + accumulate avg_probs
// block handles 64 rows; thread owns columns [tid*4, tid*4+4)
// ---------------------------------------------------------------------------
__global__ __launch_bounds__(256) void k_probs() {
    __shared__ float wsum[8];
    const int tid  = threadIdx.x;
    const int lane = tid & 31;
    const int w    = tid >> 5;
    const size_t rowBase = (size_t)blockIdx.x * 64;
    float pacc[4] = {0.f, 0.f, 0.f, 0.f};

    for (int r = 0; r < 64; r++) {
        const size_t row = rowBase + r;
        const float m = g_rowmin[row];
        float4 d = *(const float4*)(g_dist + row * (size_t)C_CODES + tid * 4);
        float e0 = __expf(m - d.x);
        float e1 = __expf(m - d.y);
        float e2 = __expf(m - d.z);
        float e3 = __expf(m - d.w);
        float es = (e0 + e1) + (e2 + e3);
        #pragma unroll
        for (int off = 16; off > 0; off >>= 1)
            es += __shfl_xor_sync(0xffffffffu, es, off);
        if (lane == 0) wsum[w] = es;
        __syncthreads();
        float Z = ((wsum[0] + wsum[1]) + (wsum[2] + wsum[3])) +
                  ((wsum[4] + wsum[5]) + (wsum[6] + wsum[7]));
        float inv = 1.f / Z;
        pacc[0] = fmaf(e0, inv, pacc[0]);
        pacc[1] = fmaf(e1, inv, pacc[1]);
        pacc[2] = fmaf(e2, inv, pacc[2]);
        pacc[3] = fmaf(e3, inv, pacc[3]);
        __syncthreads();
    }
    atomicAdd(&g_avg[tid * 4 + 0], pacc[0]);
    atomicAdd(&g_avg[tid * 4 + 1], pacc[1]);
    atomicAdd(&g_avg[tid * 4 + 2], pacc[2]);
    atomicAdd(&g_avg[tid * 4 + 3], pacc[3]);
}

// ---------------------------------------------------------------------------
// kernel 3: gather z_q, straight-through output, MSE partial sums
// ---------------------------------------------------------------------------
__global__ __launch_bounds__(256) void k_gather(const float* __restrict__ z,
                                                const float* __restrict__ cb,
                                                float* __restrict__ out) {
    const size_t t    = (size_t)blockIdx.x * 256 + threadIdx.x;
    const size_t base = t * 4;                     // 4 dims per thread
    const size_t row  = base >> 6;                 // /64
    const int    dpos = (int)(base & 63);
    const int    idx  = g_idx[row];

    float4 zc = *(const float4*)(z + base);
    float4 cv = *(const float4*)(cb + (size_t)idx * D_DIM + dpos);
    float dx = cv.x - zc.x, dy = cv.y - zc.y, dz = cv.z - zc.z, dw = cv.w - zc.w;
    float4 o;
    o.x = zc.x + dx; o.y = zc.y + dy; o.z = zc.z + dz; o.w = zc.w + dw;
    *(float4*)(out + base) = o;

    float s = dx * dx + dy * dy + dz * dz + dw * dw;
    #pragma unroll
    for (int off = 16; off > 0; off >>= 1)
        s += __shfl_xor_sync(0xffffffffu, s, off);
    if ((threadIdx.x & 31) == 0) atomicAdd(&g_mse, s);
}

// ---------------------------------------------------------------------------
// kernel 4: indices as float
// ---------------------------------------------------------------------------
__global__ void k_indices(float* __restrict__ out) {
    int i = blockIdx.x * 256 + threadIdx.x;
    if (i < N_ROWS) out[OUT_IDX + i] = (float)g_idx[i];
}

// ---------------------------------------------------------------------------
// kernel 5: entropy + final loss
// ---------------------------------------------------------------------------
__global__ void k_final(float* __restrict__ out) {
    __shared__ float ws[32];
    const int t = threadIdx.x;          // 1024 threads
    float p = g_avg[t] * (1.f / (float)N_ROWS);
    float e = -p * __logf(p + 1e-10f);
    #pragma unroll
    for (int off = 16; off > 0; off >>= 1)
        e += __shfl_xor_sync(0xffffffffu, e, off);
    if ((t & 31) == 0) ws[t >> 5] = e;
    __syncthreads();
    if (t < 32) {
        float v = ws[t];
        #pragma unroll
        for (int off = 16; off > 0; off >>= 1)
            v += __shfl_xor_sync(0xffffffffu, v, off);
        if (t == 0) {
            float entropy = v;
            float mse = g_mse * (1.f / (float)NZQ);
            float maxent = logf(1024.f);
            out[OUT_LOSS] = 1.25f * mse + 0.1f * (maxent - entropy) / maxent;
        }
    }
}

// ---------------------------------------------------------------------------
extern "C" void kernel_launch(void* const* d_in, const int* in_sizes, int n_in,
                              void* d_out, int out_size) {
    const float* z  = (const float*)d_in[0];
    const float* cb = (const float*)d_in[1];
    // robustness: swap if metadata ordered codebook first
    if (n_in >= 2 && in_sizes[0] == C_CODES * D_DIM && in_sizes[1] == NZQ) {
        const float* tmp = z; z = cb; cb = tmp;
    }
    float* out = (float*)d_out;

    static bool attr_done = false;
    if (!attr_done) {
        cudaFuncSetAttribute(k_dist, cudaFuncAttributeMaxDynamicSharedMemorySize,
                             (64 * 64 + 64 * 128 + 128) * (int)sizeof(float));
        attr_done = true;
    }
    const int smemBytes = (64 * 64 + 64 * 128 + 128) * (int)sizeof(float);

    k_init<<<4, 256>>>(cb);
    k_dist<<<N_ROWS / 64, 256, smemBytes>>>(z, cb);
    k_probs<<<N_ROWS / 64, 256>>>();
    k_gather<<<NZQ / 1024, 256>>>(z, cb, out);
    k_indices<<<(N_ROWS + 255) / 256, 256>>>(out);
    k_final<<<1, 1024>>>(out);
}

// round 3
// speedup vs baseline: 1.0000x; 1.0000x over previous
#include <cuda_runtime.h>
#include <math.h>

#define N_ROWS   131072            // B*K = 32*4096
#define C_CODES  1024
#define D_DIM    64
#define NZQ      8388608           // N_ROWS * D_DIM
#define OUT_LOSS NZQ               // offset of scalar loss
#define OUT_IDX  (NZQ + 1)         // offset of indices

// Scratch (device globals: allocation-free per harness rules)
__device__ float g_dist[(size_t)N_ROWS * C_CODES];   // 512 MB shifted distances
__device__ float g_rowmin[N_ROWS];
__device__ int   g_idx[N_ROWS];
__device__ float g_wsq[C_CODES];
__device__ float g_avg[C_CODES];
__device__ float g_mse;

// ---------------------------------------------------------------------------
// kernel 0: per-code squared norms + zero accumulators
// ---------------------------------------------------------------------------
__global__ void k_init(const float* __restrict__ cb) {
    int t = blockIdx.x * 256 + threadIdx.x;
    if (t < C_CODES) {
        const float4* p = (const float4*)(cb + (size_t)t * D_DIM);
        float s = 0.f;
        #pragma unroll
        for (int q = 0; q < D_DIM / 4; q++) {
            float4 v = p[q];
            s += v.x * v.x + v.y * v.y + v.z * v.z + v.w * v.w;
        }
        g_wsq[t] = s;
        g_avg[t] = 0.f;
    }
    if (t == 0) g_mse = 0.f;
}

// ---------------------------------------------------------------------------
// kernel 1: distance GEMM + argmin/min, spill shifted distances to scratch
// block: 256 threads, 64 rows x 1024 codes (8 chunks of 128 codes)
// warp w owns rows [w*8, w*8+8); lane owns codes [lane*4, lane*4+4) per chunk
// ---------------------------------------------------------------------------
__global__ __launch_bounds__(256) void k_dist(const float* __restrict__ z,
                                              const float* __restrict__ cb) {
    extern __shared__ float smem[];
    float* sZt = smem;                 // [64 k][64 rows]   16 KB (transposed)
    float* sB  = smem + 64 * 64;       // [64 k][128 codes] 32 KB (transposed)
    float* sW  = smem + 64 * 64 + 64 * 128;  // [128]        0.5 KB

    const int tid  = threadIdx.x;
    const int lane = tid & 31;
    const int w    = tid >> 5;         // warp id 0..7
    const int w8   = w * 8;
    const int lane4 = lane * 4;
    const size_t rowBase = (size_t)blockIdx.x * 64;

    // load z tile, transposed: sZt[k][r]
    {
        int r  = tid & 63;
        int kq = tid >> 6;             // 0..3, 16 k's each
        const float4* zp = (const float4*)(z + (rowBase + r) * D_DIM);
        #pragma unroll
        for (int q = 0; q < 4; q++) {
            float4 v = zp[kq * 4 + q];
            int k0 = kq * 16 + q * 4;
            sZt[(k0 + 0) * 64 + r] = v.x;
            sZt[(k0 + 1) * 64 + r] = v.y;
            sZt[(k0 + 2) * 64 + r] = v.z;
            sZt[(k0 + 3) * 64 + r] = v.w;
        }
    }

    float bestd[8];
    int   bestc[8];
    #pragma unroll
    for (int i = 0; i < 8; i++) { bestd[i] = 3.4e38f; bestc[i] = 0; }

    #pragma unroll 1
    for (int ch = 0; ch < 8; ch++) {
        __syncthreads();   // also covers initial z-tile visibility
        // load codebook chunk, transposed: sB[k][c]
        {
            int c  = tid & 127;
            int kq = tid >> 7;         // 0..1, 32 k's each
            const float4* bp = (const float4*)(cb + (size_t)(ch * 128 + c) * D_DIM);
            #pragma unroll
            for (int q = 0; q < 8; q++) {
                float4 v = bp[kq * 8 + q];
                int k0 = kq * 32 + q * 4;
                sB[(k0 + 0) * 128 + c] = v.x;
                sB[(k0 + 1) * 128 + c] = v.y;
                sB[(k0 + 2) * 128 + c] = v.z;
                sB[(k0 + 3) * 128 + c] = v.w;
            }
            if (tid < 128) sW[tid] = g_wsq[ch * 128 + tid];
        }
        __syncthreads();

        float acc[8][4];
        #pragma unroll
        for (int i = 0; i < 8; i++)
            #pragma unroll
            for (int j = 0; j < 4; j++) acc[i][j] = 0.f;

        #pragma unroll 8
        for (int k = 0; k < 64; k++) {
            float4 a0 = *(const float4*)&sZt[k * 64 + w8];
            float4 a1 = *(const float4*)&sZt[k * 64 + w8 + 4];
            float4 bb = *(const float4*)&sB[k * 128 + lane4];
            float a_[8] = {a0.x, a0.y, a0.z, a0.w, a1.x, a1.y, a1.z, a1.w};
            float b_[4] = {bb.x, bb.y, bb.z, bb.w};
            #pragma unroll
            for (int i = 0; i < 8; i++)
                #pragma unroll
                for (int j = 0; j < 4; j++)
                    acc[i][j] = fmaf(a_[i], b_[j], acc[i][j]);
        }

        // epilogue: shifted dist = ||w||^2 - 2*dot ; track min/argmin; spill
        const int cbase = ch * 128 + lane4;
        const float w0 = sW[lane4 + 0], w1 = sW[lane4 + 1];
        const float w2 = sW[lane4 + 2], w3 = sW[lane4 + 3];
        #pragma unroll
        for (int i = 0; i < 8; i++) {
            float4 dv;
            dv.x = fmaf(-2.f, acc[i][0], w0);
            dv.y = fmaf(-2.f, acc[i][1], w1);
            dv.z = fmaf(-2.f, acc[i][2], w2);
            dv.w = fmaf(-2.f, acc[i][3], w3);
            if (dv.x < bestd[i]) { bestd[i] = dv.x; bestc[i] = cbase + 0; }
            if (dv.y < bestd[i]) { bestd[i] = dv.y; bestc[i] = cbase + 1; }
            if (dv.z < bestd[i]) { bestd[i] = dv.z; bestc[i] = cbase + 2; }
            if (dv.w < bestd[i]) { bestd[i] = dv.w; bestc[i] = cbase + 3; }
            *(float4*)(g_dist + (rowBase + w8 + i) * (size_t)C_CODES + cbase) = dv;
        }
    }

    // warp-level argmin reduce (tie -> smaller index, matching jnp.argmin)
    #pragma unroll
    for (int i = 0; i < 8; i++) {
        float d = bestd[i];
        int   c = bestc[i];
        #pragma unroll
        for (int off = 16; off > 0; off >>= 1) {
            float od = __shfl_xor_sync(0xffffffffu, d, off);
            int   oc = __shfl_xor_sync(0xffffffffu, c, off);
            if (od < d || (od == d && oc < c)) { d = od; c = oc; }
        }
        if (lane == 0) {
            g_rowmin[rowBase + w8 + i] = d;
            g_idx[rowBase + w8 + i]    = c;
        }
    }
}

// ---------------------------------------------------------------------------
// kernel 2: per-row softmax Z + accumulate avg_probs
// block handles 64 rows; thread owns columns [tid*4, tid*4+4)
// ---------------------------------------------------------------------------
__global__ __launch_bounds__(256) void k_probs() {
    __shared__ float wsum[8];
    const int tid  = threadIdx.x;
    const int lane = tid & 31;
    const int w    = tid >> 5;
    const size_t rowBase = (size_t)blockIdx.x * 64;
    float pacc[4] = {0.f, 0.f, 0.f, 0.f};

    for (int r = 0; r < 64; r++) {
        const size_t row = rowBase + r;
        const float m = g_rowmin[row];
        float4 d = *(const float4*)(g_dist + row * (size_t)C_CODES + tid * 4);
        float e0 = __expf(m - d.x);
        float e1 = __expf(m - d.y);
        float e2 = __expf(m - d.z);
        float e3 = __expf(m - d.w);
        float es = (e0 + e1) + (e2 + e3);
        #pragma unroll
        for (int off = 16; off > 0; off >>= 1)
            es += __shfl_xor_sync(0xffffffffu, es, off);
        if (lane == 0) wsum[w] = es;
        __syncthreads();
        float Z = ((wsum[0] + wsum[1]) + (wsum[2] + wsum[3])) +
                  ((wsum[4] + wsum[5]) + (wsum[6] + wsum[7]));
        float inv = 1.f / Z;
        pacc[0] = fmaf(e0, inv, pacc[0]);
        pacc[1] = fmaf(e1, inv, pacc[1]);
        pacc[2] = fmaf(e2, inv, pacc[2]);
        pacc[3] = fmaf(e3, inv, pacc[3]);
        __syncthreads();
    }
    atomicAdd(&g_avg[tid * 4 + 0], pacc[0]);
    atomicAdd(&g_avg[tid * 4 + 1], pacc[1]);
    atomicAdd(&g_avg[tid * 4 + 2], pacc[2]);
    atomicAdd(&g_avg[tid * 4 + 3], pacc[3]);
}

// ---------------------------------------------------------------------------
// kernel 3: gather z_q, straight-through output, MSE partial sums
// ---------------------------------------------------------------------------
__global__ __launch_bounds__(256) void k_gather(const float* __restrict__ z,
                                                const float* __restrict__ cb,
                                                float* __restrict__ out) {
    const size_t t    = (size_t)blockIdx.x * 256 + threadIdx.x;
    const size_t base = t * 4;                     // 4 dims per thread
    const size_t row  = base >> 6;                 // /64
    const int    dpos = (int)(base & 63);
    const int    idx  = g_idx[row];

    float4 zc = *(const float4*)(z + base);
    float4 cv = *(const float4*)(cb + (size_t)idx * D_DIM + dpos);
    float dx = cv.x - zc.x, dy = cv.y - zc.y, dz = cv.z - zc.z, dw = cv.w - zc.w;
    float4 o;
    o.x = zc.x + dx; o.y = zc.y + dy; o.z = zc.z + dz; o.w = zc.w + dw;
    *(float4*)(out + base) = o;

    float s = dx * dx + dy * dy + dz * dz + dw * dw;
    #pragma unroll
    for (int off = 16; off > 0; off >>= 1)
        s += __shfl_xor_sync(0xffffffffu, s, off);
    if ((threadIdx.x & 31) == 0) atomicAdd(&g_mse, s);
}

// ---------------------------------------------------------------------------
// kernel 4: indices as float
// ---------------------------------------------------------------------------
__global__ void k_indices(float* __restrict__ out) {
    int i = blockIdx.x * 256 + threadIdx.x;
    if (i < N_ROWS) out[OUT_IDX + i] = (float)g_idx[i];
}

// ---------------------------------------------------------------------------
// kernel 5: entropy + final loss
// ---------------------------------------------------------------------------
__global__ void k_final(float* __restrict__ out) {
    __shared__ float ws[32];
    const int t = threadIdx.x;          // 1024 threads
    float p = g_avg[t] * (1.f / (float)N_ROWS);
    float e = -p * __logf(p + 1e-10f);
    #pragma unroll
    for (int off = 16; off > 0; off >>= 1)
        e += __shfl_xor_sync(0xffffffffu, e, off);
    if ((t & 31) == 0) ws[t >> 5] = e;
    __syncthreads();
    if (t < 32) {
        float v = ws[t];
        #pragma unroll
        for (int off = 16; off > 0; off >>= 1)
            v += __shfl_xor_sync(0xffffffffu, v, off);
        if (t == 0) {
            float entropy = v;
            float mse = g_mse * (1.f / (float)NZQ);
            float maxent = logf(1024.f);
            out[OUT_LOSS] = 1.25f * mse + 0.1f * (maxent - entropy) / maxent;
        }
    }
}

// ---------------------------------------------------------------------------
extern "C" void kernel_launch(void* const* d_in, const int* in_sizes, int n_in,
                              void* d_out, int out_size) {
    const float* z  = (const float*)d_in[0];
    const float* cb = (const float*)d_in[1];
    // robustness: swap if metadata ordered codebook first
    if (n_in >= 2 && in_sizes[0] == C_CODES * D_DIM && in_sizes[1] == NZQ) {
        const float* tmp = z; z = cb; cb = tmp;
    }
    float* out = (float*)d_out;

    static bool attr_done = false;
    if (!attr_done) {
        cudaFuncSetAttribute(k_dist, cudaFuncAttributeMaxDynamicSharedMemorySize,
                             (64 * 64 + 64 * 128 + 128) * (int)sizeof(float));
        attr_done = true;
    }
    const int smemBytes = (64 * 64 + 64 * 128 + 128) * (int)sizeof(float);

    k_init<<<4, 256>>>(cb);
    k_dist<<<N_ROWS / 64, 256, smemBytes>>>(z, cb);
    k_probs<<<N_ROWS / 64, 256>>>();
    k_gather<<<NZQ / 1024, 256>>>(z, cb, out);
    k_indices<<<(N_ROWS + 255) / 256, 256>>>(out);
    k_final<<<1, 1024>>>(out);
}

// round 4
// speedup vs baseline: 1.0041x; 1.0040x over previous
#include <cuda_runtime.h>
#include <math.h>

#define N_ROWS   131072            // B*K = 32*4096
#define C_CODES  1024
#define D_DIM    64
#define NZQ      8388608           // N_ROWS * D_DIM
#define OUT_LOSS NZQ               // offset of scalar loss
#define OUT_IDX  (NZQ + 1)         // offset of indices

// Scratch (device globals: allocation-free per harness rules)
__device__ float g_dist[(size_t)N_ROWS * C_CODES];   // 512 MB shifted distances
__device__ float g_rowmin[N_ROWS];
__device__ int   g_idx[N_ROWS];
__device__ float g_wsq[C_CODES];
__device__ float g_avg[C_CODES];
__device__ float g_mse;

// ---------------------------------------------------------------------------
// kernel 0: per-code squared norms + zero accumulators
// ---------------------------------------------------------------------------
__global__ void k_init(const float* __restrict__ cb) {
    int t = blockIdx.x * 256 + threadIdx.x;
    if (t < C_CODES) {
        const float4* p = (const float4*)(cb + (size_t)t * D_DIM);
        float s = 0.f;
        #pragma unroll
        for (int q = 0; q < D_DIM / 4; q++) {
            float4 v = p[q];
            s += v.x * v.x + v.y * v.y + v.z * v.z + v.w * v.w;
        }
        g_wsq[t] = s;
        g_avg[t] = 0.f;
    }
    if (t == 0) g_mse = 0.f;
}

// ---------------------------------------------------------------------------
// kernel 1: distance GEMM + argmin/min, spill shifted distances to scratch
// block: 256 threads, 64 rows x 1024 codes (8 chunks of 128 codes)
// warp w owns rows [w*8, w*8+8); lane owns codes [lane*4, lane*4+4) per chunk
// ---------------------------------------------------------------------------
__global__ __launch_bounds__(256) void k_dist(const float* __restrict__ z,
                                              const float* __restrict__ cb) {
    extern __shared__ float smem[];
    float* sZt = smem;                 // [64 k][64 rows]   16 KB (transposed)
    float* sB  = smem + 64 * 64;       // [64 k][128 codes] 32 KB (transposed)
    float* sW  = smem + 64 * 64 + 64 * 128;  // [128]        0.5 KB

    const int tid  = threadIdx.x;
    const int lane = tid & 31;
    const int w    = tid >> 5;         // warp id 0..7
    const int w8   = w * 8;
    const int lane4 = lane * 4;
    const size_t rowBase = (size_t)blockIdx.x * 64;

    // load z tile, transposed: sZt[k][r]
    {
        int r  = tid & 63;
        int kq = tid >> 6;             // 0..3, 16 k's each
        const float4* zp = (const float4*)(z + (rowBase + r) * D_DIM);
        #pragma unroll
        for (int q = 0; q < 4; q++) {
            float4 v = zp[kq * 4 + q];
            int k0 = kq * 16 + q * 4;
            sZt[(k0 + 0) * 64 + r] = v.x;
            sZt[(k0 + 1) * 64 + r] = v.y;
            sZt[(k0 + 2) * 64 + r] = v.z;
            sZt[(k0 + 3) * 64 + r] = v.w;
        }
    }

    float bestd[8];
    int   bestc[8];
    #pragma unroll
    for (int i = 0; i < 8; i++) { bestd[i] = 3.4e38f; bestc[i] = 0; }

    #pragma unroll 1
    for (int ch = 0; ch < 8; ch++) {
        __syncthreads();   // also covers initial z-tile visibility
        // load codebook chunk, transposed: sB[k][c]
        {
            int c  = tid & 127;
            int kq = tid >> 7;         // 0..1, 32 k's each
            const float4* bp = (const float4*)(cb + (size_t)(ch * 128 + c) * D_DIM);
            #pragma unroll
            for (int q = 0; q < 8; q++) {
                float4 v = bp[kq * 8 + q];
                int k0 = kq * 32 + q * 4;
                sB[(k0 + 0) * 128 + c] = v.x;
                sB[(k0 + 1) * 128 + c] = v.y;
                sB[(k0 + 2) * 128 + c] = v.z;
                sB[(k0 + 3) * 128 + c] = v.w;
            }
            if (tid < 128) sW[tid] = g_wsq[ch * 128 + tid];
        }
        __syncthreads();

        float acc[8][4];
        #pragma unroll
        for (int i = 0; i < 8; i++)
            #pragma unroll
            for (int j = 0; j < 4; j++) acc[i][j] = 0.f;

        #pragma unroll 8
        for (int k = 0; k < 64; k++) {
            float4 a0 = *(const float4*)&sZt[k * 64 + w8];
            float4 a1 = *(const float4*)&sZt[k * 64 + w8 + 4];
            float4 bb = *(const float4*)&sB[k * 128 + lane4];
            float a_[8] = {a0.x, a0.y, a0.z, a0.w, a1.x, a1.y, a1.z, a1.w};
            float b_[4] = {bb.x, bb.y, bb.z, bb.w};
            #pragma unroll
            for (int i = 0; i < 8; i++)
                #pragma unroll
                for (int j = 0; j < 4; j++)
                    acc[i][j] = fmaf(a_[i], b_[j], acc[i][j]);
        }

        // epilogue: shifted dist = ||w||^2 - 2*dot ; track min/argmin; spill
        const int cbase = ch * 128 + lane4;
        const float w0 = sW[lane4 + 0], w1 = sW[lane4 + 1];
        const float w2 = sW[lane4 + 2], w3 = sW[lane4 + 3];
        #pragma unroll
        for (int i = 0; i < 8; i++) {
            float4 dv;
            dv.x = fmaf(-2.f, acc[i][0], w0);
            dv.y = fmaf(-2.f, acc[i][1], w1);
            dv.z = fmaf(-2.f, acc[i][2], w2);
            dv.w = fmaf(-2.f, acc[i][3], w3);
            if (dv.x < bestd[i]) { bestd[i] = dv.x; bestc[i] = cbase + 0; }
            if (dv.y < bestd[i]) { bestd[i] = dv.y; bestc[i] = cbase + 1; }
            if (dv.z < bestd[i]) { bestd[i] = dv.z; bestc[i] = cbase + 2; }
            if (dv.w < bestd[i]) { bestd[i] = dv.w; bestc[i] = cbase + 3; }
            *(float4*)(g_dist + (rowBase + w8 + i) * (size_t)C_CODES + cbase) = dv;
        }
    }

    // warp-level argmin reduce (tie -> smaller index, matching jnp.argmin)
    #pragma unroll
    for (int i = 0; i < 8; i++) {
        float d = bestd[i];
        int   c = bestc[i];
        #pragma unroll
        for (int off = 16; off > 0; off >>= 1) {
            float od = __shfl_xor_sync(0xffffffffu, d, off);
            int   oc = __shfl_xor_sync(0xffffffffu, c, off);
            if (od < d || (od == d && oc < c)) { d = od; c = oc; }
        }
        if (lane == 0) {
            g_rowmin[rowBase + w8 + i] = d;
            g_idx[rowBase + w8 + i]    = c;
        }
    }
}

// ---------------------------------------------------------------------------
// kernel 2: per-row softmax Z + accumulate avg_probs
// block handles 64 rows; thread owns columns [tid*4, tid*4+4)
// ---------------------------------------------------------------------------
__global__ __launch_bounds__(256) void k_probs() {
    __shared__ float wsum[8];
    const int tid  = threadIdx.x;
    const int lane = tid & 31;
    const int w    = tid >> 5;
    const size_t rowBase = (size_t)blockIdx.x * 64;
    float pacc[4] = {0.f, 0.f, 0.f, 0.f};

    for (int r = 0; r < 64; r++) {
        const size_t row = rowBase + r;
        const float m = g_rowmin[row];
        float4 d = *(const float4*)(g_dist + row * (size_t)C_CODES + tid * 4);
        float e0 = __expf(m - d.x);
        float e1 = __expf(m - d.y);
        float e2 = __expf(m - d.z);
        float e3 = __expf(m - d.w);
        float es = (e0 + e1) + (e2 + e3);
        #pragma unroll
        for (int off = 16; off > 0; off >>= 1)
            es += __shfl_xor_sync(0xffffffffu, es, off);
        if (lane == 0) wsum[w] = es;
        __syncthreads();
        float Z = ((wsum[0] + wsum[1]) + (wsum[2] + wsum[3])) +
                  ((wsum[4] + wsum[5]) + (wsum[6] + wsum[7]));
        float inv = 1.f / Z;
        pacc[0] = fmaf(e0, inv, pacc[0]);
        pacc[1] = fmaf(e1, inv, pacc[1]);
        pacc[2] = fmaf(e2, inv, pacc[2]);
        pacc[3] = fmaf(e3, inv, pacc[3]);
        __syncthreads();
    }
    atomicAdd(&g_avg[tid * 4 + 0], pacc[0]);
    atomicAdd(&g_avg[tid * 4 + 1], pacc[1]);
    atomicAdd(&g_avg[tid * 4 + 2], pacc[2]);
    atomicAdd(&g_avg[tid * 4 + 3], pacc[3]);
}

// ---------------------------------------------------------------------------
// kernel 3: gather z_q, straight-through output, MSE partial sums
// ---------------------------------------------------------------------------
__global__ __launch_bounds__(256) void k_gather(const float* __restrict__ z,
                                                const float* __restrict__ cb,
                                                float* __restrict__ out) {
    const size_t t    = (size_t)blockIdx.x * 256 + threadIdx.x;
    const size_t base = t * 4;                     // 4 dims per thread
    const size_t row  = base >> 6;                 // /64
    const int    dpos = (int)(base & 63);
    const int    idx  = g_idx[row];

    float4 zc = *(const float4*)(z + base);
    float4 cv = *(const float4*)(cb + (size_t)idx * D_DIM + dpos);
    float dx = cv.x - zc.x, dy = cv.y - zc.y, dz = cv.z - zc.z, dw = cv.w - zc.w;
    float4 o;
    o.x = zc.x + dx; o.y = zc.y + dy; o.z = zc.z + dz; o.w = zc.w + dw;
    *(float4*)(out + base) = o;

    float s = dx * dx + dy * dy + dz * dz + dw * dw;
    #pragma unroll
    for (int off = 16; off > 0; off >>= 1)
        s += __shfl_xor_sync(0xffffffffu, s, off);
    if ((threadIdx.x & 31) == 0) atomicAdd(&g_mse, s);
}

// ---------------------------------------------------------------------------
// kernel 4: indices as float
// ---------------------------------------------------------------------------
__global__ void k_indices(float* __restrict__ out) {
    int i = blockIdx.x * 256 + threadIdx.x;
    if (i < N_ROWS) out[OUT_IDX + i] = (float)g_idx[i];
}

// ---------------------------------------------------------------------------
// kernel 5: entropy + final loss
// ---------------------------------------------------------------------------
__global__ void k_final(float* __restrict__ out) {
    __shared__ float ws[32];
    const int t = threadIdx.x;          // 1024 threads
    float p = g_avg[t] * (1.f / (float)N_ROWS);
    float e = -p * __logf(p + 1e-10f);
    #pragma unroll
    for (int off = 16; off > 0; off >>= 1)
        e += __shfl_xor_sync(0xffffffffu, e, off);
    if ((t & 31) == 0) ws[t >> 5] = e;
    __syncthreads();
    if (t < 32) {
        float v = ws[t];
        #pragma unroll
        for (int off = 16; off > 0; off >>= 1)
            v += __shfl_xor_sync(0xffffffffu, v, off);
        if (t == 0) {
            float entropy = v;
            float mse = g_mse * (1.f / (float)NZQ);
            float maxent = logf(1024.f);
            out[OUT_LOSS] = 1.25f * mse + 0.1f * (maxent - entropy) / maxent;
        }
    }
}

// ---------------------------------------------------------------------------
extern "C" void kernel_launch(void* const* d_in, const int* in_sizes, int n_in,
                              void* d_out, int out_size) {
    const float* z  = (const float*)d_in[0];
    const float* cb = (const float*)d_in[1];
    // robustness: swap if metadata ordered codebook first
    if (n_in >= 2 && in_sizes[0] == C_CODES * D_DIM && in_sizes[1] == NZQ) {
        const float* tmp = z; z = cb; cb = tmp;
    }
    float* out = (float*)d_out;

    static bool attr_done = false;
    if (!attr_done) {
        cudaFuncSetAttribute(k_dist, cudaFuncAttributeMaxDynamicSharedMemorySize,
                             (64 * 64 + 64 * 128 + 128) * (int)sizeof(float));
        attr_done = true;
    }
    const int smemBytes = (64 * 64 + 64 * 128 + 128) * (int)sizeof(float);

    k_init<<<4, 256>>>(cb);
    k_dist<<<N_ROWS / 64, 256, smemBytes>>>(z, cb);
    k_probs<<<N_ROWS / 64, 256>>>();
    k_gather<<<NZQ / 1024, 256>>>(z, cb, out);
    k_indices<<<(N_ROWS + 255) / 256, 256>>>(out);
    k_final<<<1, 1024>>>(out);
}